// round 4
// baseline (speedup 1.0000x reference)
#include <cuda_runtime.h>
#include <cuda_bf16.h>

// ---------------- problem constants ----------------
#define NN    1000
#define EE    8000
#define FDIM  32

// conv stage geometry
#define H0 1000
#define W0 32
#define C1 3
#define H1C 998
#define W1C 31
#define H1P 499
#define C2 6
#define H2C 497
#define W2C 30
#define H2P 248
#define C3 3
#define H3C 246
#define W3C 29
#define H3P 123
#define C4 1
#define H4C 121
#define W4C 28
#define H4P 60
#define VLEN 1680   // 60*28

// ---------------- device scratch ----------------
__device__ float g_cnt[NN];             // edge count per node (deg = 1 + cnt)
__device__ float g_hw[NN * FDIM];       // X@W (layer input transformed)
__device__ float g_acc[NN * FDIM];      // segment-sum accumulator
__device__ float g_img1[C1 * H1P * W1C];
__device__ float g_img2[C2 * H2P * W2C];
__device__ float g_img3[C3 * H3P * W3C];
__device__ float g_v[VLEN];
__device__ float g_fc1[1024];
__device__ float g_fc2[1024];

__device__ __forceinline__ float leaky(float v) {
    return v > 0.f ? v : 0.2f * v;
}

// ---------------- stage A: init + hw1 = x(:,3:6) @ W1(3:6,:) ----------------
__global__ void k_init_hw1(const float* __restrict__ x,
                           const float* __restrict__ W1) {
    int i = blockIdx.x * blockDim.x + threadIdx.x;
    if (i < NN * FDIM) {
        int n = i >> 5;        // /32
        int j = i & 31;
        float x3 = x[n * 6 + 3], x4 = x[n * 6 + 4], x5 = x[n * 6 + 5];
        float hw = x3 * W1[3 * 32 + j] + x4 * W1[4 * 32 + j] + x5 * W1[5 * 32 + j];
        g_hw[i] = hw;
        g_acc[i] = 0.f;
    }
    if (i < NN) g_cnt[i] = 0.f;
}

// ---------------- stage A2: degree counts (edge_index is INT32!) ----------
__global__ void k_deg(const int* __restrict__ ei) {
    int e = blockIdx.x * blockDim.x + threadIdx.x;
    if (e < EE) {
        int c = ei[EE + e];
        atomicAdd(&g_cnt[c], 1.0f);
    }
}

// ---------------- stage B/D: edge + self-loop scatter ----------------
// work item: warp per (edge | self-loop node), lane = feature
__global__ void k_scatter(const int* __restrict__ ei) {
    int t = blockIdx.x * blockDim.x + threadIdx.x;
    int item = t >> 5;
    int j = t & 31;
    if (item < EE) {
        int r = ei[item];
        int c = ei[EE + item];
        float norm = rsqrtf((1.f + g_cnt[r]) * (1.f + g_cnt[c]));
        atomicAdd(&g_acc[c * FDIM + j], g_hw[r * FDIM + j] * norm);
    } else if (item < EE + NN) {
        int n = item - EE;
        float inv = 1.f / (1.f + g_cnt[n]);
        atomicAdd(&g_acc[n * FDIM + j], g_hw[n * FDIM + j] * inv);
    }
}

// ---------------- stage C: h1 = leaky(acc+b1); hw2 = h1@W2; zero acc -------
__global__ void k_xform(const float* __restrict__ b1,
                        const float* __restrict__ W2) {
    int t = blockIdx.x * blockDim.x + threadIdx.x;
    int n = t >> 5;
    int j = t & 31;
    if (n >= NN) return;
    float a = g_acc[n * FDIM + j] + b1[j];
    float h = leaky(a);
    g_acc[n * FDIM + j] = 0.f;
    float s = 0.f;
#pragma unroll
    for (int k = 0; k < 32; k++) {
        float hk = __shfl_sync(0xffffffffu, h, k);
        s += hk * W2[k * 32 + j];
    }
    g_hw[n * FDIM + j] = s;
}

// ---------------- conv1 (input = leaky(acc+b2) inline) ----------------
__global__ void k_conv1(const float* __restrict__ b2,
                        const float* __restrict__ k1,
                        const float* __restrict__ kb1) {
    int idx = blockIdx.x * blockDim.x + threadIdx.x;
    if (idx >= C1 * H1P * W1C) return;
    int w = idx % W1C;
    int ph = (idx / W1C) % H1P;
    int o = idx / (W1C * H1P);
    float best = -1e30f;
#pragma unroll
    for (int rr = 0; rr < 2; rr++) {
        int h = 2 * ph + rr;
        float s = kb1[o];
#pragma unroll
        for (int kh = 0; kh < 3; kh++) {
#pragma unroll
            for (int kw = 0; kw < 2; kw++) {
                int ww = w + kw;
                float in0 = leaky(g_acc[(h + kh) * W0 + ww] + b2[ww]);
                s += in0 * k1[(o * 3 + kh) * 2 + kw];
            }
        }
        best = fmaxf(best, s);
    }
    g_img1[idx] = fmaxf(best, 0.f);
}

// ---------------- conv2 ----------------
__global__ void k_conv2(const float* __restrict__ k2,
                        const float* __restrict__ kb2) {
    int idx = blockIdx.x * blockDim.x + threadIdx.x;
    if (idx >= C2 * H2P * W2C) return;
    int w = idx % W2C;
    int ph = (idx / W2C) % H2P;
    int o = idx / (W2C * H2P);
    float best = -1e30f;
#pragma unroll
    for (int rr = 0; rr < 2; rr++) {
        int h = 2 * ph + rr;
        float s = kb2[o];
#pragma unroll
        for (int i = 0; i < 3; i++) {
#pragma unroll
            for (int kh = 0; kh < 3; kh++) {
#pragma unroll
                for (int kw = 0; kw < 2; kw++) {
                    s += g_img1[(i * H1P + h + kh) * W1C + w + kw] *
                         k2[((o * 3 + i) * 3 + kh) * 2 + kw];
                }
            }
        }
        best = fmaxf(best, s);
    }
    g_img2[idx] = fmaxf(best, 0.f);
}

// ---------------- conv3 ----------------
__global__ void k_conv3(const float* __restrict__ k3,
                        const float* __restrict__ kb3) {
    int idx = blockIdx.x * blockDim.x + threadIdx.x;
    if (idx >= C3 * H3P * W3C) return;
    int w = idx % W3C;
    int ph = (idx / W3C) % H3P;
    int o = idx / (W3C * H3P);
    float best = -1e30f;
#pragma unroll
    for (int rr = 0; rr < 2; rr++) {
        int h = 2 * ph + rr;
        float s = kb3[o];
#pragma unroll
        for (int i = 0; i < 6; i++) {
#pragma unroll
            for (int kh = 0; kh < 3; kh++) {
#pragma unroll
                for (int kw = 0; kw < 2; kw++) {
                    s += g_img2[(i * H2P + h + kh) * W2C + w + kw] *
                         k3[((o * 6 + i) * 3 + kh) * 2 + kw];
                }
            }
        }
        best = fmaxf(best, s);
    }
    g_img3[idx] = fmaxf(best, 0.f);
}

// ---------------- conv4 -> v ----------------
__global__ void k_conv4(const float* __restrict__ k4,
                        const float* __restrict__ kb4) {
    int idx = blockIdx.x * blockDim.x + threadIdx.x;
    if (idx >= H4P * W4C) return;
    int w = idx % W4C;
    int ph = idx / W4C;
    float best = -1e30f;
#pragma unroll
    for (int rr = 0; rr < 2; rr++) {
        int h = 2 * ph + rr;
        float s = kb4[0];
#pragma unroll
        for (int i = 0; i < 3; i++) {
#pragma unroll
            for (int kh = 0; kh < 3; kh++) {
#pragma unroll
                for (int kw = 0; kw < 2; kw++) {
                    s += g_img3[(i * H3P + h + kh) * W3C + w + kw] *
                         k4[(i * 3 + kh) * 2 + kw];
                }
            }
        }
        best = fmaxf(best, s);
    }
    g_v[idx] = fmaxf(best, 0.f);
}

// ---------------- FC layers: warp per output row ----------------
// y[r] = sum_k in[k]*W[r*K+k] + b[r]; in/out are device globals referenced
// directly (no symbol-address API — not allowed by harness).
template <int K>
__device__ __forceinline__ void fc_body(const float* __restrict__ W,
                                        const float* __restrict__ b,
                                        const float* __restrict__ in,
                                        float* __restrict__ out, int rows) {
    __shared__ float sv[K];
    int tid = threadIdx.x;
    for (int k = tid; k < K; k += blockDim.x) sv[k] = in[k];
    __syncthreads();
    int warp = (blockIdx.x * blockDim.x + tid) >> 5;
    int lane = tid & 31;
    if (warp >= rows) return;
    const float* wr = W + (long)warp * K;
    float s = 0.f;
    for (int k = lane; k < K; k += 32) s += wr[k] * sv[k];
#pragma unroll
    for (int off = 16; off > 0; off >>= 1)
        s += __shfl_down_sync(0xffffffffu, s, off);
    if (lane == 0) out[warp] = s + b[warp];
}

__global__ void k_fc1(const float* __restrict__ W, const float* __restrict__ b) {
    fc_body<VLEN>(W, b, g_v, g_fc1, 1024);
}
__global__ void k_fc2(const float* __restrict__ W, const float* __restrict__ b) {
    fc_body<1024>(W, b, g_fc1, g_fc2, 1024);
}
__global__ void k_fc3(const float* __restrict__ W, const float* __restrict__ b,
                      float* __restrict__ out) {
    fc_body<1024>(W, b, g_fc2, out, 64);
}

// ---------------- launch ----------------
extern "C" void kernel_launch(void* const* d_in, const int* in_sizes, int n_in,
                              void* d_out, int out_size) {
    const float* x   = (const float*)d_in[0];
    const int*   ei  = (const int*)d_in[1];       // int64 in reference -> int32 here
    const float* W1  = (const float*)d_in[2];
    const float* b1  = (const float*)d_in[3];
    const float* W2  = (const float*)d_in[4];
    const float* b2  = (const float*)d_in[5];
    const float* k1  = (const float*)d_in[6];
    const float* kb1 = (const float*)d_in[7];
    const float* k2  = (const float*)d_in[8];
    const float* kb2 = (const float*)d_in[9];
    const float* k3  = (const float*)d_in[10];
    const float* kb3 = (const float*)d_in[11];
    const float* k4  = (const float*)d_in[12];
    const float* kb4 = (const float*)d_in[13];
    const float* fw1 = (const float*)d_in[14];
    const float* fb1 = (const float*)d_in[15];
    const float* fw2 = (const float*)d_in[16];
    const float* fb2 = (const float*)d_in[17];
    const float* fw3 = (const float*)d_in[18];
    const float* fb3 = (const float*)d_in[19];
    float* out = (float*)d_out;

    const int B = 256;
    k_init_hw1<<<(NN * FDIM + B - 1) / B, B>>>(x, W1);
    k_deg<<<(EE + B - 1) / B, B>>>(ei);
    k_scatter<<<((EE + NN) * 32 + B - 1) / B, B>>>(ei);
    k_xform<<<(NN * 32 + B - 1) / B, B>>>(b1, W2);
    k_scatter<<<((EE + NN) * 32 + B - 1) / B, B>>>(ei);
    k_conv1<<<(C1 * H1P * W1C + B - 1) / B, B>>>(b2, k1, kb1);
    k_conv2<<<(C2 * H2P * W2C + B - 1) / B, B>>>(k2, kb2);
    k_conv3<<<(C3 * H3P * W3C + B - 1) / B, B>>>(k3, kb3);
    k_conv4<<<(H4P * W4C + B - 1) / B, B>>>(k4, kb4);
    k_fc1<<<128, 256>>>(fw1, fb1);
    k_fc2<<<128, 256>>>(fw2, fb2);
    k_fc3<<<8, 256>>>(fw3, fb3, out);
}